// round 13
// baseline (speedup 1.0000x reference)
#include <cuda_runtime.h>
#include <math.h>

// Shape fixed by reference: [4,1,128,256,256] fp32
#define IMG_W    256
#define IMG_H    256
#define NSLICES  512                  // B*D
#define STRIP_H  32                   // rows per block
#define STRIPS   (IMG_H / STRIP_H)    // 8
#define NB       (NSLICES * STRIPS)   // 4096 blocks
#define YT       2                    // y groups per block (256 thr = 128 x * 2 y)
#define NR       (STRIP_H / YT)       // 16 output rows per thread
#define N_TOTAL  (4.0 * 128.0 * 256.0 * 256.0)

__device__ float        g_partials[NB];
__device__ unsigned int g_count = 0;

__device__ __forceinline__ float sqrt_approx(float x) {
    float r; asm("sqrt.approx.f32 %0, %1;" : "=f"(r) : "f"(x)); return r;
}

struct Row4 { float n0, n1, n2, n3; };   // cols [cb-1, cb, cb+1, cb+2]

// Raw loads: one aligned float2 + two independent halo scalars (L1 hits —
// same 128B lines as neighbors' vectors). When row_ok is the literal `true`
// (clean path) every guard folds away -> unconditional LDGs, zero SETP/SEL.
__device__ __forceinline__ Row4 load_row2(const float* __restrict__ p,
                                          bool row_ok, bool has_l, bool has_r)
{
    Row4 o;
    float2 v = make_float2(0.f, 0.f);
    float  l = 0.f, r = 0.f;
    if (row_ok) {
        v = *reinterpret_cast<const float2*>(p);
        if (has_l) l = p[-1];
        if (has_r) r = p[2];
    }
    o.n0 = l; o.n1 = v.x; o.n2 = v.y; o.n3 = r;
    return o;
}

// Separable row aggregates for 2 columns:
//   h1 = r - l        (ex = h1[y-1] + 2h1[y] + h1[y+1])
//   h2 = l + 2m + r   (ey = h2[y+1] - h2[y-1])
__device__ __forceinline__ void row_agg2(const Row4& n, float h1[2], float h2[2])
{
    h1[0] = n.n2 - n.n0;  h2[0] = fmaf(2.f, n.n1, n.n0 + n.n2);
    h1[1] = n.n3 - n.n1;  h2[1] = fmaf(2.f, n.n2, n.n1 + n.n3);
}

// Whole per-thread strip. GUARD=false: window fully interior, all row
// predicates are compile-time true, all offsets compile-time constants.
template<bool GUARD>
__device__ __forceinline__ float compute_strip(const float* __restrict__ P,
                                               const float* __restrict__ T,
                                               int r0, bool has_l, bool has_r)
{
    float ph1p[2], ph2p[2], ph1c[2], ph2c[2];
    float th1p[2], th2p[2], th1c[2], th2c[2];

    {
        const bool top_ok = GUARD ? (r0 > 0) : true;
        const Row4 pp = load_row2(P - IMG_W, top_ok, has_l, has_r);
        const Row4 tp = load_row2(T - IMG_W, top_ok, has_l, has_r);
        const Row4 pc = load_row2(P, true, has_l, has_r);
        const Row4 tc = load_row2(T, true, has_l, has_r);
        row_agg2(pp, ph1p, ph2p);
        row_agg2(tp, th1p, th2p);
        row_agg2(pc, ph1c, ph2c);
        row_agg2(tc, th1c, th2c);
    }

    // Prefetch first body row (r0+1). (r0+1 < IMG_H always: r0 <= 240.)
    Row4 pcur = load_row2(P + IMG_W, true, has_l, has_r);
    Row4 tcur = load_row2(T + IMG_W, true, has_l, has_r);

    float acc = 0.f;

    #pragma unroll
    for (int i = 0; i < NR; i++) {
        // Prefetch row r0+2+i while computing on (pcur, tcur).
        // Constant (2+i)*IMG_W folds into the LDG immediate offset.
        const bool nok = GUARD ? (r0 + 2 + i < IMG_H) : true;
        const Row4 pnxt = load_row2(P + (2 + i) * IMG_W, nok, has_l, has_r);
        const Row4 tnxt = load_row2(T + (2 + i) * IMG_W, nok, has_l, has_r);

        float ph1n[2], ph2n[2], th1n[2], th2n[2];
        row_agg2(pcur, ph1n, ph2n);
        row_agg2(tcur, th1n, th2n);

        #pragma unroll
        for (int j = 0; j < 2; j++) {
            float ex = fmaf(2.f, ph1c[j], ph1p[j]) + ph1n[j];
            float ey = ph2n[j] - ph2p[j];
            const float magp = sqrt_approx(fmaf(ex, ex, fmaf(ey, ey, 1e-8f)));

            ex = fmaf(2.f, th1c[j], th1p[j]) + th1n[j];
            ey = th2n[j] - th2p[j];
            const float magt = sqrt_approx(fmaf(ex, ex, fmaf(ey, ey, 1e-8f)));

            acc += fabsf(magp - magt);
        }

        #pragma unroll
        for (int j = 0; j < 2; j++) {
            ph1p[j] = ph1c[j]; ph1c[j] = ph1n[j];
            ph2p[j] = ph2c[j]; ph2c[j] = ph2n[j];
            th1p[j] = th1c[j]; th1c[j] = th1n[j];
            th2p[j] = th2c[j]; th2c[j] = th2n[j];
        }
        pcur = pnxt; tcur = tnxt;
    }
    return acc;
}

__global__ __launch_bounds__(256, 6)
void edge_loss_kernel(const float* __restrict__ pred,
                      const float* __restrict__ target,
                      float* __restrict__ out)
{
    __shared__ float warp_sums[8];
    __shared__ int   s_last;

    const int tid  = threadIdx.x;
    const int xt   = tid & 127;           // 0..127 -> cols [2xt, 2xt+1]
    const int ty   = tid >> 7;            // 0..1
    const int lane = tid & 31;
    const int cb   = xt << 1;
    const bool has_l = (xt != 0);
    const bool has_r = (xt != 127);

    const int r0 = blockIdx.x * STRIP_H + ty * NR;

    const size_t base = (size_t)blockIdx.y * (IMG_H * IMG_W);
    const float* __restrict__ P = pred + base + cb + (size_t)r0 * IMG_W;
    const float* __restrict__ T = target + base + cb + (size_t)r0 * IMG_W;

    // Interior window [r0-1, r0+NR] fully inside the image?
    // (warp-uniform: ty is constant per warp, blockIdx.x per block)
    const bool clean = (r0 > 0) && (r0 + NR < IMG_H);

    float acc = clean ? compute_strip<false>(P, T, r0, has_l, has_r)
                      : compute_strip<true >(P, T, r0, has_l, has_r);

    // ---- Deterministic block reduction ----
    #pragma unroll
    for (int offr = 16; offr > 0; offr >>= 1)
        acc += __shfl_down_sync(0xffffffffu, acc, offr);
    if (lane == 0) warp_sums[tid >> 5] = acc;
    __syncthreads();

    if (tid == 0) {
        float s = 0.f;
        #pragma unroll
        for (int i = 0; i < 8; i++) s += warp_sums[i];
        g_partials[blockIdx.y * gridDim.x + blockIdx.x] = s;
        __threadfence();
        const unsigned old = atomicAdd(&g_count, 1u);
        s_last = (old == NB - 1) ? 1 : 0;
    }
    __syncthreads();

    // ---- Last block: deterministic final reduce (fixed order, double) ----
    if (s_last) {
        __shared__ double dred[256];
        double s = 0.0;
        #pragma unroll 8
        for (int i = tid; i < NB; i += 256)
            s += (double)g_partials[i];
        dred[tid] = s;
        __syncthreads();
        #pragma unroll
        for (int offr = 128; offr > 0; offr >>= 1) {
            if (tid < offr) dred[tid] += dred[tid + offr];
            __syncthreads();
        }
        if (tid == 0) {
            out[0]  = (float)(dred[0] / N_TOTAL);
            g_count = 0;   // reset for next graph replay
        }
    }
}

extern "C" void kernel_launch(void* const* d_in, const int* in_sizes, int n_in,
                              void* d_out, int out_size)
{
    (void)in_sizes; (void)n_in; (void)out_size;
    const float* pred   = (const float*)d_in[0];
    const float* target = (const float*)d_in[1];
    float* out = (float*)d_out;

    dim3 grid(STRIPS, NSLICES);   // 8 x 512 = 4096 blocks
    edge_loss_kernel<<<grid, 256>>>(pred, target, out);
}